// round 1
// baseline (speedup 1.0000x reference)
#include <cuda_runtime.h>

#define BATCH 16
#define NCLS  80
#define HH    128
#define WW    128
#define HW    (HH*WW)          // 16384
#define TOPK  100
#define NBUCK 4096
#define LISTN 1024             // pow2 >= max collected candidates (~160)
#define NFLAT (NCLS*TOPK)      // 8000
#define NSORT2 8192            // pow2 >= NFLAT

// Intermediates (allocation-free scratch)
__device__ float g_scores[BATCH*NCLS*TOPK];
__device__ int   g_inds[BATCH*NCLS*TOPK];

// 3x3 local-max test against SMEM plane (SAME padding == skip OOB neighbors).
// Strict ">" neighbor test keeps ties on both sides, matching hmax==heat.
__device__ __forceinline__ bool is_local_max(const float* plane, int p, float v) {
    int y = p >> 7, x = p & (WW - 1);
    if (x > 0      && plane[p - 1]  > v) return false;
    if (x < WW - 1 && plane[p + 1]  > v) return false;
    if (y > 0) {
        const float* r = plane + p - WW;
        if (            r[0]  > v) return false;
        if (x > 0      && r[-1] > v) return false;
        if (x < WW - 1 && r[1]  > v) return false;
    }
    if (y < HH - 1) {
        const float* r = plane + p + WW;
        if (            r[0]  > v) return false;
        if (x > 0      && r[-1] > v) return false;
        if (x < WW - 1 && r[1]  > v) return false;
    }
    return true;
}

// Kernel 1: per (b,c) plane -> top-100 (score, spatial index)
__global__ __launch_bounds__(256) void topk_per_class(const float* __restrict__ heat) {
    extern __shared__ unsigned char smem_raw[];
    float* plane = (float*)smem_raw;                              // 16384 f32
    int*   hist  = (int*)(plane + HW);                            // 4096 i32
    int*   psum  = hist + NBUCK;                                  // 256 i32
    unsigned long long* list = (unsigned long long*)(psum + 256); // 1024 u64
    __shared__ int sh_tb, sh_cnt;

    const int bc  = blockIdx.x;
    const int tid = threadIdx.x;
    const float* hp = heat + (size_t)bc * HW;

    // Load plane vectorized; zero histogram
    {
        const float4* s4 = (const float4*)hp;
        float4* d4 = (float4*)plane;
        #pragma unroll
        for (int i = tid; i < HW / 4; i += 256) d4[i] = s4[i];
    }
    for (int i = tid; i < NBUCK; i += 256) hist[i] = 0;
    if (tid == 0) sh_cnt = 0;
    __syncthreads();

    // Pass A: histogram of local-max values (linear buckets over [0,1))
    for (int p = tid; p < HW; p += 256) {
        float v = plane[p];
        if (is_local_max(plane, p, v)) {
            int bkt = (int)(v * (float)NBUCK);
            bkt = max(0, min(NBUCK - 1, bkt));
            atomicAdd(&hist[bkt], 1);
        }
    }
    __syncthreads();

    // Radix-select threshold bucket tb: largest bucket with count(>=tb) >= TOPK
    {
        int part = 0;
        #pragma unroll
        for (int i = 0; i < 16; i++) part += hist[tid * 16 + i];
        psum[tid] = part;
    }
    __syncthreads();
    if (tid == 0) {
        int run = 0, tb = 0, tstar = -1, runb = 0;
        for (int t = 255; t >= 0; --t) {
            int nr = run + psum[t];
            if (nr >= TOPK) { tstar = t; runb = run; break; }
            run = nr;
        }
        if (tstar >= 0) {
            int run2 = runb;
            for (int b2 = tstar * 16 + 15; b2 >= tstar * 16; --b2) {
                run2 += hist[b2];
                if (run2 >= TOPK) { tb = b2; break; }
            }
        }
        sh_tb = tb;
    }
    __syncthreads();
    const int tb = sh_tb;

    // Pass B: collect candidates with bucket >= tb
    for (int p = tid; p < HW; p += 256) {
        float v = plane[p];
        if (is_local_max(plane, p, v)) {
            int bkt = (int)(v * (float)NBUCK);
            bkt = max(0, min(NBUCK - 1, bkt));
            if (bkt >= tb) {
                int pos = atomicAdd(&sh_cnt, 1);
                if (pos < LISTN) {
                    // key: high = value bits (nonneg floats -> monotone),
                    // low = HW-1-p so descending sort -> smaller index first on ties
                    list[pos] = ((unsigned long long)__float_as_uint(v) << 32)
                              | (unsigned)(HW - 1 - p);
                }
            }
        }
    }
    __syncthreads();
    const int n = min(sh_cnt, LISTN);
    for (int i = n + tid; i < LISTN; i += 256) list[i] = 0ULL;
    __syncthreads();

    // Bitonic sort LISTN keys, descending
    for (int k2 = 2; k2 <= LISTN; k2 <<= 1) {
        for (int j2 = k2 >> 1; j2 > 0; j2 >>= 1) {
            #pragma unroll
            for (int i = tid; i < LISTN; i += 256) {
                int ixj = i ^ j2;
                if (ixj > i) {
                    unsigned long long a = list[i], b2 = list[ixj];
                    bool desc = ((i & k2) == 0);
                    bool swap = desc ? (a < b2) : (a > b2);
                    if (swap) { list[i] = b2; list[ixj] = a; }
                }
            }
            __syncthreads();
        }
    }

    if (tid < TOPK) {
        unsigned long long kk = list[tid];
        float sc; int idx;
        if (tid < n) {
            sc  = __uint_as_float((unsigned)(kk >> 32));
            idx = HW - 1 - (int)(unsigned)(kk & 0xFFFFFFFFu);
        } else {
            sc = 0.0f; idx = 0;   // unreachable in practice (>=100 maxima always)
        }
        g_scores[bc * TOPK + tid] = sc;
        g_inds[bc * TOPK + tid]   = idx;
    }
}

// Kernel 2: per-batch global top-100 over C*K, then gather bbox
__global__ __launch_bounds__(256) void topk_global(const float* __restrict__ wh,
                                                   const float* __restrict__ reg,
                                                   float* __restrict__ out) {
    extern __shared__ unsigned long long list[];  // NSORT2 u64
    const int b = blockIdx.x, tid = threadIdx.x;

    for (int i = tid; i < NSORT2; i += 256) {
        unsigned long long key = 0ULL;
        if (i < NFLAT) {
            float s = g_scores[b * NFLAT + i];
            key = ((unsigned long long)__float_as_uint(s) << 32)
                | (unsigned)(NSORT2 - 1 - i);   // tie-break: lower flat index first
        }
        list[i] = key;
    }
    __syncthreads();

    for (int k2 = 2; k2 <= NSORT2; k2 <<= 1) {
        for (int j2 = k2 >> 1; j2 > 0; j2 >>= 1) {
            #pragma unroll
            for (int i = tid; i < NSORT2; i += 256) {
                int ixj = i ^ j2;
                if (ixj > i) {
                    unsigned long long a = list[i], c2 = list[ixj];
                    bool desc = ((i & k2) == 0);
                    bool swap = desc ? (a < c2) : (a > c2);
                    if (swap) { list[i] = c2; list[ixj] = a; }
                }
            }
            __syncthreads();
        }
    }

    if (tid < TOPK) {
        unsigned long long kk = list[tid];
        float score = __uint_as_float((unsigned)(kk >> 32));
        int flat = NSORT2 - 1 - (int)(unsigned)(kk & 0xFFFFFFFFu);  // < NFLAT always
        int cls  = flat / TOPK;
        int ind  = g_inds[b * NFLAT + flat];

        float ysf = (float)(ind >> 7);
        float xsf = (float)(ind & (WW - 1));
        const float* regb = reg + (size_t)b * 2 * HW;
        const float* whb  = wh  + (size_t)b * 2 * HW;
        float rx = regb[ind],      ry = regb[HW + ind];
        float w  = whb[ind],       h  = whb[HW + ind];
        float xb = xsf + rx, yb = ysf + ry;

        float* o = out + (size_t)(b * TOPK + tid) * 6;
        o[0] = xb - w * 0.5f;
        o[1] = yb - h * 0.5f;
        o[2] = xb + w * 0.5f;
        o[3] = yb + h * 0.5f;
        o[4] = score;
        o[5] = (float)cls;
    }
}

extern "C" void kernel_launch(void* const* d_in, const int* in_sizes, int n_in,
                              void* d_out, int out_size) {
    const float* heat = (const float*)d_in[0];
    const float* wh   = (const float*)d_in[1];
    const float* reg  = (const float*)d_in[2];
    float* out        = (float*)d_out;

    const size_t smem1 = (size_t)HW * 4 + (size_t)NBUCK * 4 + 256 * 4 + (size_t)LISTN * 8; // ~91 KB
    const size_t smem2 = (size_t)NSORT2 * 8;                                               // 64 KB

    cudaFuncSetAttribute(topk_per_class, cudaFuncAttributeMaxDynamicSharedMemorySize, (int)smem1);
    cudaFuncSetAttribute(topk_global,    cudaFuncAttributeMaxDynamicSharedMemorySize, (int)smem2);

    topk_per_class<<<BATCH * NCLS, 256, smem1>>>(heat);
    topk_global<<<BATCH, 256, smem2>>>(wh, reg, out);
}

// round 2
// speedup vs baseline: 6.8924x; 6.8924x over previous
#include <cuda_runtime.h>

#define BATCH 16
#define NCLS  80
#define HH    128
#define WW    128
#define HW    (HH*WW)          // 16384
#define TOPK  100
#define NFLAT (NCLS*TOPK)      // 8000

// kernel 1 sizes
#define T1       256
#define NB1      2048
#define CAND_CAP 4608
#define SORT1    256
// kernel 2 sizes
#define T2       256
#define NB2      4096
#define SORT2    1024
#define NSORTIDX 8192          // pow2 > NFLAT for tie-break packing

typedef unsigned long long ull;

__device__ float g_scores[BATCH*NCLS*TOPK];
__device__ int   g_inds[BATCH*NCLS*TOPK];

__device__ __forceinline__ float neginf() { return __int_as_float(0xff800000); }

// ---------------------------------------------------------------------------
// Kernel 1: one block per (b,c) plane -> exact per-class top-100.
// Separable 3x3 max stencil via register rolling window + warp shuffles.
// 256 threads = 8 warps: warp w handles columns [(w&3)*32, +32), rows half (w>>2).
// ---------------------------------------------------------------------------
__global__ __launch_bounds__(T1) void topk_per_class(const float* __restrict__ heat) {
    __shared__ ull cand[CAND_CAP];
    __shared__ int hist[NB1];
    __shared__ int psum[T1];
    __shared__ ull sbuf[SORT1];
    __shared__ int sh_cnt, sh_tb, sh_scnt;

    const int bc  = blockIdx.x;
    const int tid = threadIdx.x;
    const int lane = tid & 31;
    const int w    = tid >> 5;
    const float* __restrict__ hp = heat + (size_t)bc * HW;

    if (tid == 0) { sh_cnt = 0; sh_scnt = 0; }
    for (int i = tid; i < NB1; i += T1) hist[i] = 0;

    // ---- stencil pass (no smem plane; global reads hit L1) ----
    {
        const float NEG = neginf();
        const int cs = w & 3;          // column strip
        const int rh = w >> 2;         // row half
        const int x  = cs * 32 + lane;
        const int y0 = rh * 64, yend = y0 + 64;

        const bool hasL = (lane == 0)  && (x > 0);
        const bool hasR = (lane == 31) && (x < WW - 1);

        // rolling window registers: prev,cur rows for own column + edge columns
        float pv  = (y0 > 0) ? hp[(y0 - 1) * WW + x] : NEG;
        float cv  = hp[y0 * WW + x];
        float pvL = (hasL && y0 > 0) ? hp[(y0 - 1) * WW + x - 1] : NEG;
        float cvL = hasL ? hp[y0 * WW + x - 1] : NEG;
        float pvR = (hasR && y0 > 0) ? hp[(y0 - 1) * WW + x + 1] : NEG;
        float cvR = hasR ? hp[y0 * WW + x + 1] : NEG;

        #pragma unroll 4
        for (int y = y0; y < yend; ++y) {
            const bool hn = (y + 1 < HH);
            float nv  = hn ? hp[(y + 1) * WW + x] : NEG;
            float nvL = (hasL && hn) ? hp[(y + 1) * WW + x - 1] : NEG;
            float nvR = (hasR && hn) ? hp[(y + 1) * WW + x + 1] : NEG;

            float vm  = fmaxf(pv,  fmaxf(cv,  nv));
            float vmL = fmaxf(pvL, fmaxf(cvL, nvL));
            float vmR = fmaxf(pvR, fmaxf(cvR, nvR));

            float lft = __shfl_up_sync(0xffffffffu, vm, 1);
            if (lane == 0)  lft = vmL;                 // NEG when x==0
            float rgt = __shfl_down_sync(0xffffffffu, vm, 1);
            if (lane == 31) rgt = vmR;                 // NEG when x==WW-1

            float hm = fmaxf(vm, fmaxf(lft, rgt));
            if (cv >= hm) {   // cv equals window max (non-strict, matches hmax==heat)
                int pos = atomicAdd(&sh_cnt, 1);
                if (pos < CAND_CAP) {
                    int p = y * WW + x;
                    cand[pos] = ((ull)__float_as_uint(cv) << 32)
                              | (unsigned)(HW - 1 - p);
                }
            }
            pv = cv; cv = nv; pvL = cvL; cvL = nvL; pvR = cvR; cvR = nvR;
        }
    }
    __syncthreads();
    const int n = min(sh_cnt, CAND_CAP);

    // ---- histogram of candidate values (linear over [0,1)) ----
    for (int i = tid; i < n; i += T1) {
        float v = __uint_as_float((unsigned)(cand[i] >> 32));
        int b = (int)(v * (float)NB1);
        b = max(0, min(NB1 - 1, b));
        atomicAdd(&hist[b], 1);
    }
    __syncthreads();

    // ---- radix-select threshold bucket for rank TOPK ----
    {
        int part = 0;
        #pragma unroll
        for (int i = 0; i < NB1 / T1; i++) part += hist[tid * (NB1 / T1) + i];
        psum[tid] = part;
    }
    __syncthreads();
    if (tid == 0) {
        int run = 0, tb = 0;
        for (int t = T1 - 1; t >= 0; --t) {
            int nr = run + psum[t];
            if (nr >= TOPK || t == 0) {
                int r2 = run;
                int base = t * (NB1 / T1);
                tb = base;
                for (int b2 = base + (NB1 / T1) - 1; b2 >= base; --b2) {
                    r2 += hist[b2];
                    if (r2 >= TOPK) { tb = b2; break; }
                }
                break;
            }
            run = nr;
        }
        sh_tb = tb;
    }
    __syncthreads();
    const int tb = sh_tb;

    // ---- collect survivors (~107), pad, bitonic sort 256 desc ----
    for (int i = tid; i < n; i += T1) {
        float v = __uint_as_float((unsigned)(cand[i] >> 32));
        int b = (int)(v * (float)NB1);
        b = max(0, min(NB1 - 1, b));
        if (b >= tb) {
            int pos = atomicAdd(&sh_scnt, 1);
            if (pos < SORT1) sbuf[pos] = cand[i];
        }
    }
    __syncthreads();
    const int sc = min(sh_scnt, SORT1);
    for (int i = sc + tid; i < SORT1; i += T1) sbuf[i] = 0ULL;
    __syncthreads();

    #pragma unroll
    for (int k2 = 2; k2 <= SORT1; k2 <<= 1) {
        #pragma unroll
        for (int j2 = k2 >> 1; j2 > 0; j2 >>= 1) {
            int i = tid;
            int ixj = i ^ j2;
            if (ixj > i) {
                ull a = sbuf[i], b2 = sbuf[ixj];
                bool desc = ((i & k2) == 0);
                if (desc ? (a < b2) : (a > b2)) { sbuf[i] = b2; sbuf[ixj] = a; }
            }
            __syncthreads();
        }
    }

    if (tid < TOPK) {
        ull kk = sbuf[tid];
        float scv = __uint_as_float((unsigned)(kk >> 32));
        int idx = HW - 1 - (int)(unsigned)(kk & 0xFFFFFFFFu);
        g_scores[bc * TOPK + tid] = scv;
        g_inds[bc * TOPK + tid]   = idx;
    }
}

// ---------------------------------------------------------------------------
// Kernel 2: per-batch global top-100 over C*K via histogram select, then gather
// ---------------------------------------------------------------------------
__global__ __launch_bounds__(T2) void topk_global(const float* __restrict__ wh,
                                                  const float* __restrict__ reg,
                                                  float* __restrict__ out) {
    __shared__ int hist[NB2];
    __shared__ int psum[T2];
    __shared__ ull sbuf[SORT2];
    __shared__ int sh_tb, sh_scnt;

    const int b = blockIdx.x, tid = threadIdx.x;
    const float* __restrict__ sc = g_scores + b * NFLAT;

    for (int i = tid; i < NB2; i += T2) hist[i] = 0;
    if (tid == 0) sh_scnt = 0;
    __syncthreads();

    for (int i = tid; i < NFLAT; i += T2) {
        float v = sc[i];
        int bk = (int)(v * (float)NB2);
        bk = max(0, min(NB2 - 1, bk));
        atomicAdd(&hist[bk], 1);
    }
    __syncthreads();

    {
        int part = 0;
        #pragma unroll
        for (int i = 0; i < NB2 / T2; i++) part += hist[tid * (NB2 / T2) + i];
        psum[tid] = part;
    }
    __syncthreads();
    if (tid == 0) {
        int run = 0, tb = 0;
        for (int t = T2 - 1; t >= 0; --t) {
            int nr = run + psum[t];
            if (nr >= TOPK || t == 0) {
                int r2 = run;
                int base = t * (NB2 / T2);
                tb = base;
                for (int b2 = base + (NB2 / T2) - 1; b2 >= base; --b2) {
                    r2 += hist[b2];
                    if (r2 >= TOPK) { tb = b2; break; }
                }
                break;
            }
            run = nr;
        }
        sh_tb = tb;
    }
    __syncthreads();
    const int tb = sh_tb;

    for (int i = tid; i < NFLAT; i += T2) {
        float v = sc[i];
        int bk = (int)(v * (float)NB2);
        bk = max(0, min(NB2 - 1, bk));
        if (bk >= tb) {
            int pos = atomicAdd(&sh_scnt, 1);
            if (pos < SORT2)
                sbuf[pos] = ((ull)__float_as_uint(v) << 32)
                          | (unsigned)(NSORTIDX - 1 - i);   // tie-break: lower flat idx first
        }
    }
    __syncthreads();
    const int scn = min(sh_scnt, SORT2);
    for (int i = scn + tid; i < SORT2; i += T2) sbuf[i] = 0ULL;
    __syncthreads();

    for (int k2 = 2; k2 <= SORT2; k2 <<= 1) {
        for (int j2 = k2 >> 1; j2 > 0; j2 >>= 1) {
            #pragma unroll
            for (int i = tid; i < SORT2; i += T2) {
                int ixj = i ^ j2;
                if (ixj > i) {
                    ull a = sbuf[i], c2 = sbuf[ixj];
                    bool desc = ((i & k2) == 0);
                    if (desc ? (a < c2) : (a > c2)) { sbuf[i] = c2; sbuf[ixj] = a; }
                }
            }
            __syncthreads();
        }
    }

    if (tid < TOPK) {
        ull kk = sbuf[tid];
        float score = __uint_as_float((unsigned)(kk >> 32));
        int flat = NSORTIDX - 1 - (int)(unsigned)(kk & 0xFFFFFFFFu);
        int cls  = flat / TOPK;
        int ind  = g_inds[b * NFLAT + flat];

        float ysf = (float)(ind >> 7);
        float xsf = (float)(ind & (WW - 1));
        const float* regb = reg + (size_t)b * 2 * HW;
        const float* whb  = wh  + (size_t)b * 2 * HW;
        float rx = regb[ind], ry = regb[HW + ind];
        float ww = whb[ind],  hh = whb[HW + ind];
        float xb = xsf + rx, yb = ysf + ry;

        float* o = out + (size_t)(b * TOPK + tid) * 6;
        o[0] = xb - ww * 0.5f;
        o[1] = yb - hh * 0.5f;
        o[2] = xb + ww * 0.5f;
        o[3] = yb + hh * 0.5f;
        o[4] = score;
        o[5] = (float)cls;
    }
}

extern "C" void kernel_launch(void* const* d_in, const int* in_sizes, int n_in,
                              void* d_out, int out_size) {
    const float* heat = (const float*)d_in[0];
    const float* wh   = (const float*)d_in[1];
    const float* reg  = (const float*)d_in[2];
    float* out        = (float*)d_out;

    topk_per_class<<<BATCH * NCLS, T1>>>(heat);
    topk_global<<<BATCH, T2>>>(wh, reg, out);
}

// round 3
// speedup vs baseline: 13.7123x; 1.9895x over previous
#include <cuda_runtime.h>

#define BATCH 16
#define NCLS  80
#define HH    128
#define WW    128
#define HW    (HH*WW)          // 16384
#define TOPK  100
#define NFLAT (NCLS*TOPK)      // 8000

// kernel 1 sizes
#define T1       256
#define NB1      2048
#define CAND_CAP 3072          // expected ~1820 candidates (theoretical max 4096, iid ~1820±40)
#define SORT1    256
// kernel 2 sizes
#define T2       512
#define NB2      4096
#define SORT2    1024
#define NSORTIDX 8192          // pow2 > NFLAT for tie-break packing

typedef unsigned long long ull;

__device__ float g_scores[BATCH*NCLS*TOPK];
__device__ int   g_inds[BATCH*NCLS*TOPK];

__device__ __forceinline__ float neginf() { return __int_as_float(0xff800000); }

// ---------------------------------------------------------------------------
// Kernel 1: one block per (b,c) plane -> exact per-class top-100.
// float4 rolling-window separable 3x3 max; warp = full 128-col row.
// ---------------------------------------------------------------------------
__global__ __launch_bounds__(T1) void topk_per_class(const float* __restrict__ heat) {
    __shared__ ull cand[CAND_CAP];
    __shared__ int hist[NB1];
    __shared__ int psum[T1];
    __shared__ ull sbuf[SORT1];
    __shared__ int sh_cnt, sh_tb, sh_scnt;

    const int bc   = blockIdx.x;
    const int tid  = threadIdx.x;
    const int lane = tid & 31;
    const int w    = tid >> 5;          // warp 0..7
    const float* __restrict__ hp = heat + (size_t)bc * HW;

    if (tid == 0) { sh_cnt = 0; sh_scnt = 0; }
    for (int i = tid; i < NB1; i += T1) hist[i] = 0;

    // ---- stencil pass: warp w owns rows [w*16, w*16+16), lane owns cols [4*lane,4*lane+4)
    {
        const float NEG = neginf();
        const float4 NEG4 = make_float4(NEG, NEG, NEG, NEG);
        const int y0 = w * 16, yend = y0 + 16;
        const float4* __restrict__ hp4 = (const float4*)hp;

        float4 pv = (y0 > 0) ? hp4[(y0 - 1) * 32 + lane] : NEG4;
        float4 cv = hp4[y0 * 32 + lane];

        #pragma unroll 4
        for (int y = y0; y < yend; ++y) {
            float4 nv = (y + 1 < HH) ? hp4[(y + 1) * 32 + lane] : NEG4;

            float4 vm;
            vm.x = fmaxf(pv.x, fmaxf(cv.x, nv.x));
            vm.y = fmaxf(pv.y, fmaxf(cv.y, nv.y));
            vm.z = fmaxf(pv.z, fmaxf(cv.z, nv.z));
            vm.w = fmaxf(pv.w, fmaxf(cv.w, nv.w));

            float vmL = __shfl_up_sync(0xffffffffu, vm.w, 1);
            if (lane == 0)  vmL = NEG;      // x==0 boundary
            float vmR = __shfl_down_sync(0xffffffffu, vm.x, 1);
            if (lane == 31) vmR = NEG;      // x==127 boundary

            float hm0 = fmaxf(vmL,  fmaxf(vm.x, vm.y));
            float hm1 = fmaxf(vm.x, fmaxf(vm.y, vm.z));
            float hm2 = fmaxf(vm.y, fmaxf(vm.z, vm.w));
            float hm3 = fmaxf(vm.z, fmaxf(vm.w, vmR));

            const int p = y * WW + lane * 4;
            if (cv.x >= hm0) {
                int pos = atomicAdd(&sh_cnt, 1);
                if (pos < CAND_CAP)
                    cand[pos] = ((ull)__float_as_uint(cv.x) << 32) | (unsigned)(HW - 1 - p);
            }
            if (cv.y >= hm1) {
                int pos = atomicAdd(&sh_cnt, 1);
                if (pos < CAND_CAP)
                    cand[pos] = ((ull)__float_as_uint(cv.y) << 32) | (unsigned)(HW - 1 - (p + 1));
            }
            if (cv.z >= hm2) {
                int pos = atomicAdd(&sh_cnt, 1);
                if (pos < CAND_CAP)
                    cand[pos] = ((ull)__float_as_uint(cv.z) << 32) | (unsigned)(HW - 1 - (p + 2));
            }
            if (cv.w >= hm3) {
                int pos = atomicAdd(&sh_cnt, 1);
                if (pos < CAND_CAP)
                    cand[pos] = ((ull)__float_as_uint(cv.w) << 32) | (unsigned)(HW - 1 - (p + 3));
            }
            pv = cv; cv = nv;
        }
    }
    __syncthreads();
    const int n = min(sh_cnt, CAND_CAP);

    // ---- histogram of candidate values (linear over [0,1)) ----
    for (int i = tid; i < n; i += T1) {
        float v = __uint_as_float((unsigned)(cand[i] >> 32));
        int b = (int)(v * (float)NB1);
        b = max(0, min(NB1 - 1, b));
        atomicAdd(&hist[b], 1);
    }
    __syncthreads();

    // ---- select threshold bucket for rank TOPK (early-exit serial scan) ----
    {
        int part = 0;
        #pragma unroll
        for (int i = 0; i < NB1 / T1; i++) part += hist[tid * (NB1 / T1) + i];
        psum[tid] = part;
    }
    __syncthreads();
    if (tid == 0) {
        int run = 0, tb = 0;
        for (int t = T1 - 1; t >= 0; --t) {
            int nr = run + psum[t];
            if (nr >= TOPK || t == 0) {
                int r2 = run;
                int base = t * (NB1 / T1);
                tb = base;
                for (int b2 = base + (NB1 / T1) - 1; b2 >= base; --b2) {
                    r2 += hist[b2];
                    if (r2 >= TOPK) { tb = b2; break; }
                }
                break;
            }
            run = nr;
        }
        sh_tb = tb;
    }
    __syncthreads();
    const int tb = sh_tb;

    // ---- collect survivors (~115) ----
    for (int i = tid; i < n; i += T1) {
        ull kk = cand[i];
        float v = __uint_as_float((unsigned)(kk >> 32));
        int b = (int)(v * (float)NB1);
        b = max(0, min(NB1 - 1, b));
        if (b >= tb) {
            int pos = atomicAdd(&sh_scnt, 1);
            if (pos < SORT1) sbuf[pos] = kk;
        }
    }
    __syncthreads();
    const int s = min(sh_scnt, SORT1);

    // ---- rank-by-count (no barriers, keys unique) ----
    if (tid < s) {
        ull mykey = sbuf[tid];
        int rank = 0;
        for (int j = 0; j < s; ++j) rank += (sbuf[j] > mykey);
        if (rank < TOPK) {
            g_scores[bc * TOPK + rank] = __uint_as_float((unsigned)(mykey >> 32));
            g_inds[bc * TOPK + rank]   = HW - 1 - (int)(unsigned)(mykey & 0xFFFFFFFFu);
        }
    }
}

// ---------------------------------------------------------------------------
// Kernel 2: per-batch global top-100 over C*K via histogram select + rank-count
// ---------------------------------------------------------------------------
__global__ __launch_bounds__(T2) void topk_global(const float* __restrict__ wh,
                                                  const float* __restrict__ reg,
                                                  float* __restrict__ out) {
    __shared__ int hist[NB2];
    __shared__ int psum[T2];
    __shared__ ull sbuf[SORT2];
    __shared__ int sh_tb, sh_scnt;

    const int b = blockIdx.x, tid = threadIdx.x;
    const float* __restrict__ sc = g_scores + b * NFLAT;

    for (int i = tid; i < NB2; i += T2) hist[i] = 0;
    if (tid == 0) sh_scnt = 0;
    __syncthreads();

    for (int i = tid; i < NFLAT; i += T2) {
        float v = sc[i];
        int bk = (int)(v * (float)NB2);
        bk = max(0, min(NB2 - 1, bk));
        atomicAdd(&hist[bk], 1);
    }
    __syncthreads();

    {
        int part = 0;
        #pragma unroll
        for (int i = 0; i < NB2 / T2; i++) part += hist[tid * (NB2 / T2) + i];
        psum[tid] = part;
    }
    __syncthreads();
    if (tid == 0) {
        int run = 0, tb = 0;
        for (int t = T2 - 1; t >= 0; --t) {
            int nr = run + psum[t];
            if (nr >= TOPK || t == 0) {
                int r2 = run;
                int base = t * (NB2 / T2);
                tb = base;
                for (int b2 = base + (NB2 / T2) - 1; b2 >= base; --b2) {
                    r2 += hist[b2];
                    if (r2 >= TOPK) { tb = b2; break; }
                }
                break;
            }
            run = nr;
        }
        sh_tb = tb;
    }
    __syncthreads();
    const int tb = sh_tb;

    for (int i = tid; i < NFLAT; i += T2) {
        float v = sc[i];
        int bk = (int)(v * (float)NB2);
        bk = max(0, min(NB2 - 1, bk));
        if (bk >= tb) {
            int pos = atomicAdd(&sh_scnt, 1);
            if (pos < SORT2)
                sbuf[pos] = ((ull)__float_as_uint(v) << 32)
                          | (unsigned)(NSORTIDX - 1 - i);   // lower flat idx wins ties
        }
    }
    __syncthreads();
    const int s = min(sh_scnt, SORT2);

    // ---- rank-by-count + gather/bbox for the winners ----
    for (int i = tid; i < s; i += T2) {
        ull mykey = sbuf[i];
        int rank = 0;
        for (int j = 0; j < s; ++j) rank += (sbuf[j] > mykey);
        if (rank < TOPK) {
            float score = __uint_as_float((unsigned)(mykey >> 32));
            int flat = NSORTIDX - 1 - (int)(unsigned)(mykey & 0xFFFFFFFFu);
            int cls  = flat / TOPK;
            int ind  = g_inds[b * NFLAT + flat];

            float ysf = (float)(ind >> 7);
            float xsf = (float)(ind & (WW - 1));
            const float* regb = reg + (size_t)b * 2 * HW;
            const float* whb  = wh  + (size_t)b * 2 * HW;
            float rx = regb[ind], ry = regb[HW + ind];
            float ww2 = whb[ind], hh2 = whb[HW + ind];
            float xb = xsf + rx, yb = ysf + ry;

            float* o = out + (size_t)(b * TOPK + rank) * 6;
            o[0] = xb - ww2 * 0.5f;
            o[1] = yb - hh2 * 0.5f;
            o[2] = xb + ww2 * 0.5f;
            o[3] = yb + hh2 * 0.5f;
            o[4] = score;
            o[5] = (float)cls;
        }
    }
}

extern "C" void kernel_launch(void* const* d_in, const int* in_sizes, int n_in,
                              void* d_out, int out_size) {
    const float* heat = (const float*)d_in[0];
    const float* wh   = (const float*)d_in[1];
    const float* reg  = (const float*)d_in[2];
    float* out        = (float*)d_out;

    topk_per_class<<<BATCH * NCLS, T1>>>(heat);
    topk_global<<<BATCH, T2>>>(wh, reg, out);
}

// round 5
// speedup vs baseline: 14.4264x; 1.0521x over previous
#include <cuda_runtime.h>

#define BATCH 16
#define NCLS  80
#define HH    128
#define WW    128
#define HW    (HH*WW)          // 16384
#define TOPK  100
#define NFLAT (NCLS*TOPK)      // 8000
#define NBLK  (BATCH*NCLS)     // 1280

#define T1       256           // threads per block
#define CAP1     512           // class-phase fast-path survivor cap
#define CAP2     1024          // global-phase fast-path survivor cap
#define FB_CAP   3072          // fallback candidate cap per plane
#define NBH      2048          // fallback histogram bins (aliased into sbuf)
#define NSORTIDX 8192          // pow2 > NFLAT for tie-break packing

#define THR_CLASS  0.985f      // E[cnt]=231 of 16384/9, P(cnt<100) ~ 8 sigma
#define THR_GLOBAL 0.9997f     // E[cnt]=393 of 8000

typedef unsigned long long ull;

__device__ float g_scores[BATCH*NFLAT];
__device__ int   g_inds[BATCH*NFLAT];
__device__ int   g_done[BATCH];                       // zero-init; finisher resets
__device__ ull   g_cand[(size_t)NBLK * FB_CAP];       // fallback scratch only

__device__ __forceinline__ float neginf() { return __int_as_float(0xff800000); }

// Separable 3x3-max stencil over one 128x128 plane.
// warp w owns rows [w*16, w*16+16); lane owns cols [4*lane, 4*lane+4).
// Appends packed keys (valbits<<32 | HW-1-p) for local maxima passing the
// value filter (ALL=true: every local max; ALL=false: v >= THR_CLASS).
template<bool ALL>
__device__ __forceinline__ void stencil_pass(const float* __restrict__ hp,
                                             int lane, int w,
                                             ull* dst, int cap, int* counter) {
    const float NEG = neginf();
    const float4 NEG4 = make_float4(NEG, NEG, NEG, NEG);
    const int y0 = w * 16, yend = y0 + 16;
    const float4* __restrict__ hp4 = (const float4*)hp;

    float4 pv = (y0 > 0) ? hp4[(y0 - 1) * 32 + lane] : NEG4;
    float4 cv = hp4[y0 * 32 + lane];

    #pragma unroll 4
    for (int y = y0; y < yend; ++y) {
        float4 nv = (y + 1 < HH) ? hp4[(y + 1) * 32 + lane] : NEG4;

        float4 vm;
        vm.x = fmaxf(pv.x, fmaxf(cv.x, nv.x));
        vm.y = fmaxf(pv.y, fmaxf(cv.y, nv.y));
        vm.z = fmaxf(pv.z, fmaxf(cv.z, nv.z));
        vm.w = fmaxf(pv.w, fmaxf(cv.w, nv.w));

        float vmL = __shfl_up_sync(0xffffffffu, vm.w, 1);
        if (lane == 0)  vmL = NEG;
        float vmR = __shfl_down_sync(0xffffffffu, vm.x, 1);
        if (lane == 31) vmR = NEG;

        float hm0 = fmaxf(vmL,  fmaxf(vm.x, vm.y));
        float hm1 = fmaxf(vm.x, fmaxf(vm.y, vm.z));
        float hm2 = fmaxf(vm.y, fmaxf(vm.z, vm.w));
        float hm3 = fmaxf(vm.z, fmaxf(vm.w, vmR));

        const int p = y * WW + lane * 4;
        if ((ALL || cv.x >= THR_CLASS) && cv.x >= hm0) {
            int pos = atomicAdd(counter, 1);
            if (pos < cap) dst[pos] = ((ull)__float_as_uint(cv.x) << 32) | (unsigned)(HW - 1 - p);
        }
        if ((ALL || cv.y >= THR_CLASS) && cv.y >= hm1) {
            int pos = atomicAdd(counter, 1);
            if (pos < cap) dst[pos] = ((ull)__float_as_uint(cv.y) << 32) | (unsigned)(HW - 1 - (p + 1));
        }
        if ((ALL || cv.z >= THR_CLASS) && cv.z >= hm2) {
            int pos = atomicAdd(counter, 1);
            if (pos < cap) dst[pos] = ((ull)__float_as_uint(cv.z) << 32) | (unsigned)(HW - 1 - (p + 2));
        }
        if ((ALL || cv.w >= THR_CLASS) && cv.w >= hm3) {
            int pos = atomicAdd(counter, 1);
            if (pos < cap) dst[pos] = ((ull)__float_as_uint(cv.w) << 32) | (unsigned)(HW - 1 - (p + 3));
        }
        pv = cv; cv = nv;
    }
}

__global__ __launch_bounds__(T1) void centerhead_fused(const float* __restrict__ heat,
                                                       const float* __restrict__ wh,
                                                       const float* __restrict__ reg,
                                                       float* __restrict__ out) {
    __shared__ ull sbuf[CAP2];        // 8 KB; fallback aliases first 8 KB as hist[2048]
    __shared__ int psum[T1];
    __shared__ int sh_cnt, sh_tb, sh_flag;
    int* hist = (int*)sbuf;

    const int bc   = blockIdx.x;
    const int b    = bc / NCLS;
    const int tid  = threadIdx.x;
    const int lane = tid & 31;
    const int w    = tid >> 5;
    const float* __restrict__ hp = heat + (size_t)bc * HW;

    if (tid == 0) sh_cnt = 0;
    __syncthreads();

    // ============ per-class phase ============
    stencil_pass<false>(hp, lane, w, sbuf, CAP1, &sh_cnt);
    __syncthreads();
    int s = sh_cnt;

    if (s < TOPK || s > CAP1) {
        // ---- exact fallback: re-scan collecting all local maxima to global scratch
        __syncthreads();
        if (tid == 0) sh_cnt = 0;
        __syncthreads();
        ull* fc = g_cand + (size_t)bc * FB_CAP;
        stencil_pass<true>(hp, lane, w, fc, FB_CAP, &sh_cnt);
        __syncthreads();
        const int n = min(sh_cnt, FB_CAP);

        for (int i = tid; i < NBH; i += T1) hist[i] = 0;
        __syncthreads();
        for (int i = tid; i < n; i += T1) {
            float v = __uint_as_float((unsigned)(fc[i] >> 32));
            int bk = (int)(v * (float)NBH);
            bk = max(0, min(NBH - 1, bk));
            atomicAdd(&hist[bk], 1);
        }
        __syncthreads();
        {
            int part = 0;
            #pragma unroll
            for (int i = 0; i < NBH / T1; i++) part += hist[tid * (NBH / T1) + i];
            psum[tid] = part;
        }
        __syncthreads();
        if (tid == 0) {
            int run = 0, tb = 0;
            for (int t = T1 - 1; t >= 0; --t) {
                int nr = run + psum[t];
                if (nr >= TOPK || t == 0) {
                    int r2 = run, base = t * (NBH / T1);
                    tb = base;
                    for (int b2 = base + (NBH / T1) - 1; b2 >= base; --b2) {
                        r2 += hist[b2];
                        if (r2 >= TOPK) { tb = b2; break; }
                    }
                    break;
                }
                run = nr;
            }
            sh_tb = tb; sh_cnt = 0;
        }
        __syncthreads();
        const int tb = sh_tb;
        for (int i = tid; i < n; i += T1) {     // survivors overwrite hist region (done with it)
            ull kk = fc[i];
            float v = __uint_as_float((unsigned)(kk >> 32));
            int bk = (int)(v * (float)NBH);
            bk = max(0, min(NBH - 1, bk));
            if (bk >= tb) {
                int pos = atomicAdd(&sh_cnt, 1);
                if (pos < CAP1) sbuf[pos] = kk;
            }
        }
        __syncthreads();
        s = min(sh_cnt, CAP1);
    }

    // rank-by-count (keys unique) -> per-class top-100, descending
    // NOTE: strided loop — s can exceed T1 (bug fixed from round 4)
    for (int i = tid; i < s; i += T1) {
        ull mykey = sbuf[i];
        int rank = 0;
        for (int j = 0; j < s; ++j) rank += (sbuf[j] > mykey);
        if (rank < TOPK) {
            g_scores[bc * TOPK + rank] = __uint_as_float((unsigned)(mykey >> 32));
            g_inds[bc * TOPK + rank]   = HW - 1 - (int)(unsigned)(mykey & 0xFFFFFFFFu);
        }
    }

    // ============ hand-off: last block of batch does the global phase ============
    __threadfence();
    __syncthreads();
    if (tid == 0) {
        int old = atomicAdd(&g_done[b], 1);
        sh_flag = (old == NCLS - 1);
    }
    __syncthreads();
    if (!sh_flag) return;
    __threadfence();   // acquire: make other blocks' g_scores/g_inds reads valid

    const float* __restrict__ sc = g_scores + b * NFLAT;

    if (tid == 0) sh_cnt = 0;
    __syncthreads();
    for (int i = tid; i < NFLAT; i += T1) {
        float v = sc[i];
        if (v >= THR_GLOBAL) {
            int pos = atomicAdd(&sh_cnt, 1);
            if (pos < CAP2)
                sbuf[pos] = ((ull)__float_as_uint(v) << 32) | (unsigned)(NSORTIDX - 1 - i);
        }
    }
    __syncthreads();
    int s2 = sh_cnt;

    if (s2 < TOPK || s2 > CAP2) {
        // ---- exact fallback: histogram select over the 8000 scores
        __syncthreads();
        for (int i = tid; i < NBH; i += T1) hist[i] = 0;
        __syncthreads();
        for (int i = tid; i < NFLAT; i += T1) {
            float v = sc[i];
            int bk = (int)(v * (float)NBH);
            bk = max(0, min(NBH - 1, bk));
            atomicAdd(&hist[bk], 1);
        }
        __syncthreads();
        {
            int part = 0;
            #pragma unroll
            for (int i = 0; i < NBH / T1; i++) part += hist[tid * (NBH / T1) + i];
            psum[tid] = part;
        }
        __syncthreads();
        if (tid == 0) {
            int run = 0, tb = 0;
            for (int t = T1 - 1; t >= 0; --t) {
                int nr = run + psum[t];
                if (nr >= TOPK || t == 0) {
                    int r2 = run, base = t * (NBH / T1);
                    tb = base;
                    for (int b2 = base + (NBH / T1) - 1; b2 >= base; --b2) {
                        r2 += hist[b2];
                        if (r2 >= TOPK) { tb = b2; break; }
                    }
                    break;
                }
                run = nr;
            }
            sh_tb = tb; sh_cnt = 0;
        }
        __syncthreads();
        const int tb = sh_tb;
        for (int i = tid; i < NFLAT; i += T1) {
            float v = sc[i];
            int bk = (int)(v * (float)NBH);
            bk = max(0, min(NBH - 1, bk));
            if (bk >= tb) {
                int pos = atomicAdd(&sh_cnt, 1);
                if (pos < CAP2)
                    sbuf[pos] = ((ull)__float_as_uint(v) << 32) | (unsigned)(NSORTIDX - 1 - i);
            }
        }
        __syncthreads();
        s2 = min(sh_cnt, CAP2);
    }

    // rank-by-count + bbox gather for winners
    for (int i = tid; i < s2; i += T1) {
        ull mykey = sbuf[i];
        int rank = 0;
        for (int j = 0; j < s2; ++j) rank += (sbuf[j] > mykey);
        if (rank < TOPK) {
            float score = __uint_as_float((unsigned)(mykey >> 32));
            int flat = NSORTIDX - 1 - (int)(unsigned)(mykey & 0xFFFFFFFFu);
            int cls  = flat / TOPK;
            int ind  = g_inds[b * NFLAT + flat];

            float ysf = (float)(ind >> 7);
            float xsf = (float)(ind & (WW - 1));
            const float* regb = reg + (size_t)b * 2 * HW;
            const float* whb  = wh  + (size_t)b * 2 * HW;
            float rx = regb[ind], ry = regb[HW + ind];
            float ww2 = whb[ind], hh2 = whb[HW + ind];
            float xb = xsf + rx, yb = ysf + ry;

            float* o = out + (size_t)(b * TOPK + rank) * 6;
            o[0] = xb - ww2 * 0.5f;
            o[1] = yb - hh2 * 0.5f;
            o[2] = xb + ww2 * 0.5f;
            o[3] = yb + hh2 * 0.5f;
            o[4] = score;
            o[5] = (float)cls;
        }
    }

    __syncthreads();
    if (tid == 0) g_done[b] = 0;   // restore for next graph replay
}

extern "C" void kernel_launch(void* const* d_in, const int* in_sizes, int n_in,
                              void* d_out, int out_size) {
    const float* heat = (const float*)d_in[0];
    const float* wh   = (const float*)d_in[1];
    const float* reg  = (const float*)d_in[2];
    float* out        = (float*)d_out;

    centerhead_fused<<<NBLK, T1>>>(heat, wh, reg, out);
}